// round 7
// baseline (speedup 1.0000x reference)
#include <cuda_runtime.h>
#include <cuda_fp16.h>
#include <cstdint>

// N=50000, E=1600000, F=128, H=128, C=64
#define NMAX 50000
#define EMAX 1600000
#define SCAN_B 1024

// Scratch (no dynamic allocation allowed)
__device__ __align__(16) float  g_dinv[NMAX];
__device__ __align__(16) int    g_count[NMAX];
__device__ __align__(16) int    g_rowstart[NMAX + 1];
__device__ __align__(16) int    g_rank[EMAX];
__device__ __align__(16) int    g_blocksum[(NMAX + SCAN_B - 1) / SCAN_B + 1];
__device__ __align__(16) int    g_srcs[EMAX];
__device__ __align__(16) __half g_msg[(size_t)NMAX * 128];    // fp16 messages (g1, then g2)
__device__ __align__(16) float  g_h1f[(size_t)NMAX * 128];    // h1f (post-relu, fp32)

// ---------------- CSR build ----------------

__global__ void k_zero_int(int* p, int n) {
    int i = blockIdx.x * blockDim.x + threadIdx.x;
    if (i < n) p[i] = 0;
}

__global__ void k_hist(const int* __restrict__ dst, int* __restrict__ count,
                       int* __restrict__ rank, int E, int n) {
    int e = blockIdx.x * blockDim.x + threadIdx.x;
    if (e < E) {
        int d = dst[e];
        int r = 0;
        if ((unsigned)d < (unsigned)n) r = atomicAdd(&count[d], 1);
        rank[e] = r;
    }
}

__global__ void k_scan1(const int* __restrict__ count, int* __restrict__ rowstart,
                        int* __restrict__ blocksum, int n) {
    __shared__ int buf[SCAN_B];
    int i = blockIdx.x * SCAN_B + threadIdx.x;
    int v = (i < n) ? count[i] : 0;
    buf[threadIdx.x] = v;
    __syncthreads();
#pragma unroll
    for (int off = 1; off < SCAN_B; off <<= 1) {
        int t = 0;
        if ((int)threadIdx.x >= off) t = buf[threadIdx.x - off];
        __syncthreads();
        if ((int)threadIdx.x >= off) buf[threadIdx.x] += t;
        __syncthreads();
    }
    if (i < n) rowstart[i] = buf[threadIdx.x] - v;
    if (threadIdx.x == SCAN_B - 1) blocksum[blockIdx.x] = buf[SCAN_B - 1];
}

__global__ void k_scan2(int* __restrict__ blocksum, int nb) {
    __shared__ int buf[SCAN_B];
    int v = (threadIdx.x < (unsigned)nb) ? blocksum[threadIdx.x] : 0;
    buf[threadIdx.x] = v;
    __syncthreads();
#pragma unroll
    for (int off = 1; off < SCAN_B; off <<= 1) {
        int t = 0;
        if ((int)threadIdx.x >= off) t = buf[threadIdx.x - off];
        __syncthreads();
        if ((int)threadIdx.x >= off) buf[threadIdx.x] += t;
        __syncthreads();
    }
    if (threadIdx.x < (unsigned)nb) blocksum[threadIdx.x] = buf[threadIdx.x] - v;
}

__global__ void k_scan3(const int* __restrict__ count, int* __restrict__ rowstart,
                        const int* __restrict__ blocksum, float* __restrict__ dinv,
                        int n, int E) {
    int i = blockIdx.x * blockDim.x + threadIdx.x;
    if (i < n) {
        rowstart[i] += blocksum[i / SCAN_B];
        dinv[i] = rsqrtf((float)count[i] + 1.0f);
    }
    if (i == 0) rowstart[n] = E;
}

__global__ void k_fill(const int* __restrict__ src, const int* __restrict__ dst,
                       const int* __restrict__ rowstart, const int* __restrict__ rank,
                       int* __restrict__ srcs, int E, int n) {
    int e = blockIdx.x * blockDim.x + threadIdx.x;
    if (e < E) {
        int d = dst[e];
        int s = src[e];
        if ((unsigned)d < (unsigned)n && (unsigned)s < (unsigned)n)
            srcs[rowstart[d] + rank[e]] = s;
    }
}

// ---------------- GEMM: msg[row][c] = half((X[row,:] @ W[:,c]) * dinv[row]) ----------------

template <int OUTC, int TN>
__global__ void k_gemm_scale_h(const float* __restrict__ X, const float* __restrict__ W,
                               const float* __restrict__ dinv, __half* __restrict__ out,
                               int N) {
    constexpr int BM = 128, BK = 8, TM = 8;
    constexpr int TCOLS = OUTC / TN;               // 16
    __shared__ float As[BK * BM];
    __shared__ float Bs[BK * OUTC];

    const int tid = threadIdx.x;
    const int tr = tid / TCOLS;
    const int tc = tid % TCOLS;
    const int rowBase = blockIdx.x * BM;

    float acc[TM][TN];
#pragma unroll
    for (int i = 0; i < TM; i++)
#pragma unroll
        for (int j = 0; j < TN; j++) acc[i][j] = 0.f;

    for (int k0 = 0; k0 < 128; k0 += BK) {
        {
            int r = tid >> 1;
            int c4 = tid & 1;
            int row = rowBase + r;
            float4 v = make_float4(0.f, 0.f, 0.f, 0.f);
            if (row < N)
                v = ((const float4*)(X + (size_t)row * 128 + k0))[c4];
            int kb = c4 * 4;
            As[(kb + 0) * BM + r] = v.x;
            As[(kb + 1) * BM + r] = v.y;
            As[(kb + 2) * BM + r] = v.z;
            As[(kb + 3) * BM + r] = v.w;
        }
        {
            constexpr int NV4 = BK * OUTC / 4;
            if (NV4 == 256 || tid < NV4) {
                int k  = tid / (OUTC / 4);
                int c4 = tid % (OUTC / 4);
                ((float4*)Bs)[tid] = ((const float4*)(W + (size_t)(k0 + k) * OUTC))[c4];
            }
        }
        __syncthreads();

#pragma unroll
        for (int k = 0; k < BK; k++) {
            float a[TM], b[TN];
#pragma unroll
            for (int i = 0; i < TM; i++) a[i] = As[k * BM + tr * TM + i];
#pragma unroll
            for (int j = 0; j < TN; j++) b[j] = Bs[k * OUTC + tc * TN + j];
#pragma unroll
            for (int i = 0; i < TM; i++)
#pragma unroll
                for (int j = 0; j < TN; j++) acc[i][j] += a[i] * b[j];
        }
        __syncthreads();
    }

#pragma unroll
    for (int i = 0; i < TM; i++) {
        int row = rowBase + tr * TM + i;
        if (row < N) {
            float dv = dinv[row];
            __half2 hv[TN / 2];
#pragma unroll
            for (int j2 = 0; j2 < TN / 2; j2++)
                hv[j2] = __floats2half2_rn(acc[i][j2 * 2] * dv, acc[i][j2 * 2 + 1] * dv);
            if (TN == 8)
                *((uint4*)(out + (size_t)row * OUTC + tc * TN)) = *((uint4*)hv);
            else
                *((uint2*)(out + (size_t)row * OUTC + tc * TN)) = *((uint2*)hv);
        }
    }
}

// ---------------- gathers: fp16 messages, fp32 accumulate, multi-edge warps ----------------

__device__ __forceinline__ void acc_u4(float* acc, uint4 u) {
    float2 p0 = __half22float2(*(const __half2*)&u.x);
    float2 p1 = __half22float2(*(const __half2*)&u.y);
    float2 p2 = __half22float2(*(const __half2*)&u.z);
    float2 p3 = __half22float2(*(const __half2*)&u.w);
    acc[0] += p0.x; acc[1] += p0.y; acc[2] += p1.x; acc[3] += p1.y;
    acc[4] += p2.x; acc[5] += p2.y; acc[6] += p3.x; acc[7] += p3.y;
}

// Layer 1: 128 cols/row. 16 lanes x uint4(8 halves) cover a row; 2 edges per warp iter.
__global__ void k_gather128h(const __half* __restrict__ g, const int* __restrict__ rowstart,
                             const int* __restrict__ srcs, const float* __restrict__ dinv,
                             const float* __restrict__ bias, float* __restrict__ out, int n) {
    int node = (blockIdx.x * blockDim.x + threadIdx.x) >> 5;
    int lane = threadIdx.x & 31;
    if (node >= n) return;
    int h   = lane >> 4;        // 0/1: which edge of the pair
    int l16 = lane & 15;        // column chunk: halves l16*8 .. +8
    int e0 = rowstart[node], e1 = rowstart[node + 1];

    float acc[8];
#pragma unroll
    for (int j = 0; j < 8; j++) acc[j] = 0.f;
    if (h == 0)  // self-loop term, counted once
        acc_u4(acc, *((const uint4*)(g + (size_t)node * 128 + l16 * 8)));

    int e = e0;
    while (e < e1) {
        int m = min(32, e1 - e);
        int idx = (lane < m) ? srcs[e + lane] : 0;
        int npair = (m + 1) >> 1;
#pragma unroll 4
        for (int k = 0; k < npair; k++) {
            int ei = 2 * k + h;
            int s = __shfl_sync(0xffffffffu, idx, ei);
            if (ei < m)
                acc_u4(acc, *((const uint4*)(g + (size_t)s * 128 + l16 * 8)));
        }
        e += m;
    }
    // combine the two half-warps (same columns)
#pragma unroll
    for (int j = 0; j < 8; j++) acc[j] += __shfl_xor_sync(0xffffffffu, acc[j], 16);

    // each lane writes 4 cols: base l16*8 + h*4
    float dv = dinv[node];
    int cb = l16 * 8 + h * 4;
    float4 bv = *((const float4*)(bias + cb));
    float4 r;
    r.x = fmaxf(acc[h * 4 + 0] * dv + bv.x, 0.f);
    r.y = fmaxf(acc[h * 4 + 1] * dv + bv.y, 0.f);
    r.z = fmaxf(acc[h * 4 + 2] * dv + bv.z, 0.f);
    r.w = fmaxf(acc[h * 4 + 3] * dv + bv.w, 0.f);
    *((float4*)(out + (size_t)node * 128 + cb)) = r;
}

// Layer 2: 64 cols/row. 8 lanes x uint4 cover a row; 4 edges per warp iter.
__global__ void k_gather64h(const __half* __restrict__ g, const int* __restrict__ rowstart,
                            const int* __restrict__ srcs, const float* __restrict__ dinv,
                            const float* __restrict__ bias, float* __restrict__ out, int n) {
    int node = (blockIdx.x * blockDim.x + threadIdx.x) >> 5;
    int lane = threadIdx.x & 31;
    if (node >= n) return;
    int q  = lane >> 3;         // 0..3: which edge of the quad
    int l8 = lane & 7;          // column chunk: halves l8*8 .. +8
    int e0 = rowstart[node], e1 = rowstart[node + 1];

    float acc[8];
#pragma unroll
    for (int j = 0; j < 8; j++) acc[j] = 0.f;
    if (q == 0)  // self-loop term
        acc_u4(acc, *((const uint4*)(g + (size_t)node * 64 + l8 * 8)));

    int e = e0;
    while (e < e1) {
        int m = min(32, e1 - e);
        int idx = (lane < m) ? srcs[e + lane] : 0;
        int nquad = (m + 3) >> 2;
#pragma unroll 4
        for (int k = 0; k < nquad; k++) {
            int ei = 4 * k + q;
            int s = __shfl_sync(0xffffffffu, idx, ei);
            if (ei < m)
                acc_u4(acc, *((const uint4*)(g + (size_t)s * 64 + l8 * 8)));
        }
        e += m;
    }
    // combine the four quarter-warps
#pragma unroll
    for (int j = 0; j < 8; j++) {
        acc[j] += __shfl_xor_sync(0xffffffffu, acc[j], 8);
        acc[j] += __shfl_xor_sync(0xffffffffu, acc[j], 16);
    }

    // each lane writes 2 cols: base l8*8 + q*2
    float dv = dinv[node];
    int cb = l8 * 8 + q * 2;
    float2 bv = *((const float2*)(bias + cb));
    float2 r;
    r.x = acc[q * 2 + 0] * dv + bv.x;
    r.y = acc[q * 2 + 1] * dv + bv.y;
    *((float2*)(out + (size_t)node * 64 + cb)) = r;
}

// ---------------- launch ----------------

extern "C" void kernel_launch(void* const* d_in, const int* in_sizes, int n_in,
                              void* d_out, int out_size) {
    const float* x   = (const float*)d_in[0];
    const int*   ei  = (const int*)d_in[1];    // int32 (JAX x64 disabled)
    const float* W1  = (const float*)d_in[2];
    const float* b1  = (const float*)d_in[3];
    const float* W2  = (const float*)d_in[4];
    const float* b2  = (const float*)d_in[5];
    float*       out = (float*)d_out;

    const int N = in_sizes[0] / 128;
    const int E = in_sizes[1] / 2;
    const int* srcp = ei;
    const int* dstp = ei + E;

    float*  dinv;  cudaGetSymbolAddress((void**)&dinv,  g_dinv);
    int*    count; cudaGetSymbolAddress((void**)&count, g_count);
    int*    rowst; cudaGetSymbolAddress((void**)&rowst, g_rowstart);
    int*    rank;  cudaGetSymbolAddress((void**)&rank,  g_rank);
    int*    bsum;  cudaGetSymbolAddress((void**)&bsum,  g_blocksum);
    int*    srcs;  cudaGetSymbolAddress((void**)&srcs,  g_srcs);
    __half* msg;   cudaGetSymbolAddress((void**)&msg,   g_msg);
    float*  h1f;   cudaGetSymbolAddress((void**)&h1f,   g_h1f);

    const int T = 256;
    const int nb = (N + SCAN_B - 1) / SCAN_B;

    // CSR build (group edges by dst) + dinv
    k_zero_int<<<(N + T - 1) / T, T>>>(count, N);
    k_hist<<<(E + T - 1) / T, T>>>(dstp, count, rank, E, N);
    k_scan1<<<nb, SCAN_B>>>(count, rowst, bsum, N);
    k_scan2<<<1, SCAN_B>>>(bsum, nb);
    k_scan3<<<(N + T - 1) / T, T>>>(count, rowst, bsum, dinv, N, E);
    k_fill<<<(E + T - 1) / T, T>>>(srcp, dstp, rowst, rank, srcs, E, N);

    // layer 1: g1 = half((x@W1)*dinv) -> msg ; h1f = relu(gather(g1)+b1) (fp32)
    k_gemm_scale_h<128, 8><<<(N + 127) / 128, 256>>>(x, W1, dinv, msg, N);
    k_gather128h<<<(N * 32 + T - 1) / T, T>>>(msg, rowst, srcs, dinv, b1, h1f, N);

    // layer 2: g2 = half((h1f@W2)*dinv) -> msg ; out = gather(g2)+b2 (fp32)
    k_gemm_scale_h<64, 4><<<(N + 127) / 128, 256>>>(h1f, W2, dinv, msg, N);
    k_gather64h<<<(N * 32 + T - 1) / T, T>>>(msg, rowst, srcs, dinv, b2, out, N);
}

// round 8
// speedup vs baseline: 1.3176x; 1.3176x over previous
#include <cuda_runtime.h>
#include <cuda_fp16.h>
#include <cstdint>

// N=50000, E=1600000, F=128, H=128, C=64
#define NMAX 50000
#define EMAX 1600000
#define SCAN_B 1024

// Scratch (no dynamic allocation allowed)
__device__ __align__(16) float  g_dinv[NMAX];
__device__ __align__(16) int    g_count[NMAX];
__device__ __align__(16) int    g_rowstart[NMAX + 1];
__device__ __align__(16) int    g_rank[EMAX];
__device__ __align__(16) int    g_blocksum[(NMAX + SCAN_B - 1) / SCAN_B + 1];
__device__ __align__(16) int    g_srcs[EMAX];
__device__ __align__(16) __half g_msg[(size_t)NMAX * 128];    // fp16 messages (g1, then g2)
__device__ __align__(16) float  g_h1f[(size_t)NMAX * 128];    // h1f (post-relu, fp32)

// ---------------- CSR build ----------------

__global__ void k_zero_int(int* p, int n) {
    int i = blockIdx.x * blockDim.x + threadIdx.x;
    if (i < n) p[i] = 0;
}

__global__ void k_hist(const int* __restrict__ dst, int* __restrict__ count,
                       int* __restrict__ rank, int E, int n) {
    int e = blockIdx.x * blockDim.x + threadIdx.x;
    if (e < E) {
        int d = dst[e];
        int r = 0;
        if ((unsigned)d < (unsigned)n) r = atomicAdd(&count[d], 1);
        rank[e] = r;
    }
}

__global__ void k_scan1(const int* __restrict__ count, int* __restrict__ rowstart,
                        int* __restrict__ blocksum, int n) {
    __shared__ int buf[SCAN_B];
    int i = blockIdx.x * SCAN_B + threadIdx.x;
    int v = (i < n) ? count[i] : 0;
    buf[threadIdx.x] = v;
    __syncthreads();
#pragma unroll
    for (int off = 1; off < SCAN_B; off <<= 1) {
        int t = 0;
        if ((int)threadIdx.x >= off) t = buf[threadIdx.x - off];
        __syncthreads();
        if ((int)threadIdx.x >= off) buf[threadIdx.x] += t;
        __syncthreads();
    }
    if (i < n) rowstart[i] = buf[threadIdx.x] - v;
    if (threadIdx.x == SCAN_B - 1) blocksum[blockIdx.x] = buf[SCAN_B - 1];
}

__global__ void k_scan2(int* __restrict__ blocksum, int nb) {
    __shared__ int buf[SCAN_B];
    int v = (threadIdx.x < (unsigned)nb) ? blocksum[threadIdx.x] : 0;
    buf[threadIdx.x] = v;
    __syncthreads();
#pragma unroll
    for (int off = 1; off < SCAN_B; off <<= 1) {
        int t = 0;
        if ((int)threadIdx.x >= off) t = buf[threadIdx.x - off];
        __syncthreads();
        if ((int)threadIdx.x >= off) buf[threadIdx.x] += t;
        __syncthreads();
    }
    if (threadIdx.x < (unsigned)nb) blocksum[threadIdx.x] = buf[threadIdx.x] - v;
}

__global__ void k_scan3(const int* __restrict__ count, int* __restrict__ rowstart,
                        const int* __restrict__ blocksum, float* __restrict__ dinv,
                        int n, int E) {
    int i = blockIdx.x * blockDim.x + threadIdx.x;
    if (i < n) {
        rowstart[i] += blocksum[i / SCAN_B];
        dinv[i] = rsqrtf((float)count[i] + 1.0f);
    }
    if (i == 0) rowstart[n] = E;
}

__global__ void k_fill(const int* __restrict__ src, const int* __restrict__ dst,
                       const int* __restrict__ rowstart, const int* __restrict__ rank,
                       int* __restrict__ srcs, int E, int n) {
    int e = blockIdx.x * blockDim.x + threadIdx.x;
    if (e < E) {
        int d = dst[e];
        int s = src[e];
        if ((unsigned)d < (unsigned)n && (unsigned)s < (unsigned)n)
            srcs[rowstart[d] + rank[e]] = s;
    }
}

// ---------------- tf32 tensor-core GEMM ----------------
// msg[row][c] = half((X[row,:128] @ W[:,c]) * dinv[row]).
// BM=128, BK=32, 256 threads = 8 warps (4M x 2N). Warp tile 32 x (OUTC/2).
// mma.sync.aligned.m16n8k8.row.col.f32.tf32.tf32.f32

__device__ __forceinline__ uint32_t f2tf32(float f) {
    uint32_t u;
    asm("cvt.rna.tf32.f32 %0, %1;" : "=r"(u) : "f"(f));
    return u;
}

template <int OUTC>
__global__ void k_gemm_tc(const float* __restrict__ X, const float* __restrict__ W,
                          const float* __restrict__ dinv, __half* __restrict__ out,
                          int N) {
    constexpr int BM = 128, BK = 32;
    constexpr int AP = 36;                 // padded A row (floats)
    constexpr int WP = OUTC + 4;           // padded W row (floats)
    constexpr int WARP_N = OUTC / 2;       // 64 or 32
    constexpr int NNT = WARP_N / 8;        // 8 or 4
    __shared__ float As[BM * AP];
    __shared__ float Ws[BK * WP];

    const int tid  = threadIdx.x;
    const int warp = tid >> 5;
    const int lane = tid & 31;
    const int wm = warp >> 1;              // 0..3
    const int wn = warp & 1;               // 0..1
    const int g   = lane >> 2;             // 0..7
    const int tig = lane & 3;              // 0..3
    const int rowBase = blockIdx.x * BM;

    float acc[2][NNT][4];
#pragma unroll
    for (int mt = 0; mt < 2; mt++)
#pragma unroll
        for (int nt = 0; nt < NNT; nt++)
#pragma unroll
            for (int c = 0; c < 4; c++) acc[mt][nt][c] = 0.f;

    for (int k0 = 0; k0 < 128; k0 += BK) {
        // load A tile: 128 rows x 32 cols, tf32-converted, padded
#pragma unroll
        for (int j = 0; j < 4; j++) {
            int i4  = tid + j * 256;       // float4 index within tile (1024 total)
            int row = i4 >> 3;
            int col = (i4 & 7) * 4;
            float4 v = make_float4(0.f, 0.f, 0.f, 0.f);
            if (rowBase + row < N)
                v = *((const float4*)(X + (size_t)(rowBase + row) * 128 + k0 + col));
            float* p = &As[row * AP + col];
            p[0] = __uint_as_float(f2tf32(v.x));
            p[1] = __uint_as_float(f2tf32(v.y));
            p[2] = __uint_as_float(f2tf32(v.z));
            p[3] = __uint_as_float(f2tf32(v.w));
        }
        // load W tile: 32 rows x OUTC cols
        {
            constexpr int F4PR = OUTC / 4;             // float4 per row
            constexpr int NJ = (BK * F4PR) / 256;      // 4 (OUTC=128) or 2 (OUTC=64)
#pragma unroll
            for (int j = 0; j < NJ; j++) {
                int i4  = tid + j * 256;
                int row = i4 / F4PR;
                int col = (i4 % F4PR) * 4;
                float4 v = *((const float4*)(W + (size_t)(k0 + row) * OUTC + col));
                float* p = &Ws[row * WP + col];
                p[0] = __uint_as_float(f2tf32(v.x));
                p[1] = __uint_as_float(f2tf32(v.y));
                p[2] = __uint_as_float(f2tf32(v.z));
                p[3] = __uint_as_float(f2tf32(v.w));
            }
        }
        __syncthreads();

#pragma unroll
        for (int kk = 0; kk < BK / 8; kk++) {
            int k = kk * 8;
            uint32_t a[2][4];
#pragma unroll
            for (int mt = 0; mt < 2; mt++) {
                int ar = wm * 32 + mt * 16;
                a[mt][0] = __float_as_uint(As[(ar + g)     * AP + k + tig]);
                a[mt][1] = __float_as_uint(As[(ar + g + 8) * AP + k + tig]);
                a[mt][2] = __float_as_uint(As[(ar + g)     * AP + k + tig + 4]);
                a[mt][3] = __float_as_uint(As[(ar + g + 8) * AP + k + tig + 4]);
            }
#pragma unroll
            for (int nt = 0; nt < NNT; nt++) {
                int nc = wn * WARP_N + nt * 8;
                uint32_t b0 = __float_as_uint(Ws[(k + tig)     * WP + nc + g]);
                uint32_t b1 = __float_as_uint(Ws[(k + tig + 4) * WP + nc + g]);
#pragma unroll
                for (int mt = 0; mt < 2; mt++) {
                    asm volatile(
                        "mma.sync.aligned.m16n8k8.row.col.f32.tf32.tf32.f32 "
                        "{%0,%1,%2,%3}, {%4,%5,%6,%7}, {%8,%9}, {%0,%1,%2,%3};"
                        : "+f"(acc[mt][nt][0]), "+f"(acc[mt][nt][1]),
                          "+f"(acc[mt][nt][2]), "+f"(acc[mt][nt][3])
                        : "r"(a[mt][0]), "r"(a[mt][1]), "r"(a[mt][2]), "r"(a[mt][3]),
                          "r"(b0), "r"(b1));
                }
            }
        }
        __syncthreads();
    }

    // epilogue: scale by dinv, convert to fp16, store
#pragma unroll
    for (int mt = 0; mt < 2; mt++) {
        int r0 = rowBase + wm * 32 + mt * 16 + g;
        int r1 = r0 + 8;
        float dv0 = (r0 < N) ? dinv[r0] : 0.f;
        float dv1 = (r1 < N) ? dinv[r1] : 0.f;
#pragma unroll
        for (int nt = 0; nt < NNT; nt++) {
            int col = wn * WARP_N + nt * 8 + tig * 2;
            if (r0 < N)
                *((__half2*)(out + (size_t)r0 * OUTC + col)) =
                    __floats2half2_rn(acc[mt][nt][0] * dv0, acc[mt][nt][1] * dv0);
            if (r1 < N)
                *((__half2*)(out + (size_t)r1 * OUTC + col)) =
                    __floats2half2_rn(acc[mt][nt][2] * dv1, acc[mt][nt][3] * dv1);
        }
    }
}

// ---------------- gathers: fp16 messages, fp32 accumulate (R6 form) ----------------

__global__ void k_gather128h(const __half* __restrict__ g, const int* __restrict__ rowstart,
                             const int* __restrict__ srcs, const float* __restrict__ dinv,
                             const float* __restrict__ bias, float* __restrict__ out, int n) {
    int node = (blockIdx.x * blockDim.x + threadIdx.x) >> 5;
    int lane = threadIdx.x & 31;
    if (node >= n) return;
    int e0 = rowstart[node], e1 = rowstart[node + 1];

    float acc0, acc1, acc2, acc3;
    {
        uint2 u = *((const uint2*)(g + (size_t)node * 128 + lane * 4));
        float2 a = __half22float2(*(const __half2*)&u.x);
        float2 b = __half22float2(*(const __half2*)&u.y);
        acc0 = a.x; acc1 = a.y; acc2 = b.x; acc3 = b.y;
    }
    int e = e0;
    while (e < e1) {
        int m = min(32, e1 - e);
        int idx = (lane < m) ? srcs[e + lane] : 0;
#pragma unroll 4
        for (int k = 0; k < m; k++) {
            int s = __shfl_sync(0xffffffffu, idx, k);
            uint2 u = *((const uint2*)(g + (size_t)s * 128 + lane * 4));
            float2 a = __half22float2(*(const __half2*)&u.x);
            float2 b = __half22float2(*(const __half2*)&u.y);
            acc0 += a.x; acc1 += a.y; acc2 += b.x; acc3 += b.y;
        }
        e += m;
    }
    float dv = dinv[node];
    float4 bv = ((const float4*)bias)[lane];
    float4 r;
    r.x = fmaxf(acc0 * dv + bv.x, 0.f);
    r.y = fmaxf(acc1 * dv + bv.y, 0.f);
    r.z = fmaxf(acc2 * dv + bv.z, 0.f);
    r.w = fmaxf(acc3 * dv + bv.w, 0.f);
    ((float4*)(out + (size_t)node * 128))[lane] = r;
}

__global__ void k_gather64h(const __half* __restrict__ g, const int* __restrict__ rowstart,
                            const int* __restrict__ srcs, const float* __restrict__ dinv,
                            const float* __restrict__ bias, float* __restrict__ out, int n) {
    int node = (blockIdx.x * blockDim.x + threadIdx.x) >> 5;
    int lane = threadIdx.x & 31;
    if (node >= n) return;
    int e0 = rowstart[node], e1 = rowstart[node + 1];

    float2 acc = __half22float2(*((const __half2*)(g + (size_t)node * 64 + lane * 2)));
    int e = e0;
    while (e < e1) {
        int m = min(32, e1 - e);
        int idx = (lane < m) ? srcs[e + lane] : 0;
#pragma unroll 4
        for (int k = 0; k < m; k++) {
            int s = __shfl_sync(0xffffffffu, idx, k);
            float2 v = __half22float2(*((const __half2*)(g + (size_t)s * 64 + lane * 2)));
            acc.x += v.x; acc.y += v.y;
        }
        e += m;
    }
    float dv = dinv[node];
    float2 bv = ((const float2*)bias)[lane];
    float2 r;
    r.x = acc.x * dv + bv.x;
    r.y = acc.y * dv + bv.y;
    ((float2*)(out + (size_t)node * 64))[lane] = r;
}

// ---------------- launch ----------------

extern "C" void kernel_launch(void* const* d_in, const int* in_sizes, int n_in,
                              void* d_out, int out_size) {
    const float* x   = (const float*)d_in[0];
    const int*   ei  = (const int*)d_in[1];    // int32 (JAX x64 disabled)
    const float* W1  = (const float*)d_in[2];
    const float* b1  = (const float*)d_in[3];
    const float* W2  = (const float*)d_in[4];
    const float* b2  = (const float*)d_in[5];
    float*       out = (float*)d_out;

    const int N = in_sizes[0] / 128;
    const int E = in_sizes[1] / 2;
    const int* srcp = ei;
    const int* dstp = ei + E;

    float*  dinv;  cudaGetSymbolAddress((void**)&dinv,  g_dinv);
    int*    count; cudaGetSymbolAddress((void**)&count, g_count);
    int*    rowst; cudaGetSymbolAddress((void**)&rowst, g_rowstart);
    int*    rank;  cudaGetSymbolAddress((void**)&rank,  g_rank);
    int*    bsum;  cudaGetSymbolAddress((void**)&bsum,  g_blocksum);
    int*    srcs;  cudaGetSymbolAddress((void**)&srcs,  g_srcs);
    __half* msg;   cudaGetSymbolAddress((void**)&msg,   g_msg);
    float*  h1f;   cudaGetSymbolAddress((void**)&h1f,   g_h1f);

    const int T = 256;
    const int nb = (N + SCAN_B - 1) / SCAN_B;

    // CSR build (group edges by dst) + dinv
    k_zero_int<<<(N + T - 1) / T, T>>>(count, N);
    k_hist<<<(E + T - 1) / T, T>>>(dstp, count, rank, E, N);
    k_scan1<<<nb, SCAN_B>>>(count, rowst, bsum, N);
    k_scan2<<<1, SCAN_B>>>(bsum, nb);
    k_scan3<<<(N + T - 1) / T, T>>>(count, rowst, bsum, dinv, N, E);
    k_fill<<<(E + T - 1) / T, T>>>(srcp, dstp, rowst, rank, srcs, E, N);

    // layer 1: g1 = half((x@W1)*dinv) -> msg ; h1f = relu(gather(g1)+b1) (fp32)
    k_gemm_tc<128><<<(N + 127) / 128, 256>>>(x, W1, dinv, msg, N);
    k_gather128h<<<(N * 32 + T - 1) / T, T>>>(msg, rowst, srcs, dinv, b1, h1f, N);

    // layer 2: g2 = half((h1f@W2)*dinv) -> msg ; out = gather(g2)+b2 (fp32)
    k_gemm_tc<64><<<(N + 127) / 128, 256>>>(h1f, W2, dinv, msg, N);
    k_gather64h<<<(N * 32 + T - 1) / T, T>>>(msg, rowst, srcs, dinv, b2, out, N);
}

// round 9
// speedup vs baseline: 1.4017x; 1.0638x over previous
#include <cuda_runtime.h>
#include <cuda_fp16.h>
#include <cstdint>

// N=50000, E=1600000, F=128, H=128, C=64
#define NMAX 50000
#define EMAX 1600000
#define SCAN_B 1024

// Scratch (no dynamic allocation allowed)
__device__ __align__(16) float  g_dinv[NMAX];
__device__ __align__(16) int    g_count[NMAX];
__device__ __align__(16) int    g_rowstart[NMAX + 1];
__device__ __align__(16) int    g_rank[EMAX];
__device__ __align__(16) int    g_blocksum[(NMAX + SCAN_B - 1) / SCAN_B + 1];
__device__ __align__(16) int    g_srcs[EMAX];
__device__ __align__(16) __half g_msg[(size_t)NMAX * 128];    // fp16 messages (g1, then g2)
__device__ __align__(16) float  g_h1f[(size_t)NMAX * 128];    // h1f (post-relu, fp32)

// ---------------- CSR build ----------------

__global__ void k_zero_int(int* p, int n) {
    int i = blockIdx.x * blockDim.x + threadIdx.x;
    if (i < n) p[i] = 0;
}

__global__ void k_hist(const int* __restrict__ dst, int* __restrict__ count,
                       int* __restrict__ rank, int E, int n) {
    int e = blockIdx.x * blockDim.x + threadIdx.x;
    if (e < E) {
        int d = dst[e];
        int r = 0;
        if ((unsigned)d < (unsigned)n) r = atomicAdd(&count[d], 1);
        rank[e] = r;
    }
}

__global__ void k_scan1(const int* __restrict__ count, int* __restrict__ rowstart,
                        int* __restrict__ blocksum, int n) {
    __shared__ int buf[SCAN_B];
    int i = blockIdx.x * SCAN_B + threadIdx.x;
    int v = (i < n) ? count[i] : 0;
    buf[threadIdx.x] = v;
    __syncthreads();
#pragma unroll
    for (int off = 1; off < SCAN_B; off <<= 1) {
        int t = 0;
        if ((int)threadIdx.x >= off) t = buf[threadIdx.x - off];
        __syncthreads();
        if ((int)threadIdx.x >= off) buf[threadIdx.x] += t;
        __syncthreads();
    }
    if (i < n) rowstart[i] = buf[threadIdx.x] - v;
    if (threadIdx.x == SCAN_B - 1) blocksum[blockIdx.x] = buf[SCAN_B - 1];
}

// single-warp shfl scan (nb small)
__global__ void k_scan2(int* __restrict__ blocksum, int nb) {
    int lane = threadIdx.x;
    int carry = 0;
    for (int base = 0; base < nb; base += 32) {
        int i = base + lane;
        int v = (i < nb) ? blocksum[i] : 0;
        int x = v;
#pragma unroll
        for (int off = 1; off < 32; off <<= 1) {
            int t = __shfl_up_sync(0xffffffffu, x, off);
            if (lane >= off) x += t;
        }
        if (i < nb) blocksum[i] = carry + x - v;   // exclusive
        carry += __shfl_sync(0xffffffffu, x, 31);
    }
}

__global__ void k_scan3(const int* __restrict__ count, int* __restrict__ rowstart,
                        const int* __restrict__ blocksum, float* __restrict__ dinv,
                        int n, int E) {
    int i = blockIdx.x * blockDim.x + threadIdx.x;
    if (i < n) {
        rowstart[i] += blocksum[i / SCAN_B];
        dinv[i] = rsqrtf((float)count[i] + 1.0f);
    }
    if (i == 0) rowstart[n] = E;
}

__global__ void k_fill(const int* __restrict__ src, const int* __restrict__ dst,
                       const int* __restrict__ rowstart, const int* __restrict__ rank,
                       int* __restrict__ srcs, int E, int n) {
    int e = blockIdx.x * blockDim.x + threadIdx.x;
    if (e < E) {
        int d = dst[e];
        int s = src[e];
        if ((unsigned)d < (unsigned)n && (unsigned)s < (unsigned)n)
            srcs[rowstart[d] + rank[e]] = s;
    }
}

// ---------------- tf32 tensor-core GEMM ----------------
// out[row][c] = half((X[row,:128] @ W[:,c]) * (SCALE ? dinv[row] : 1))
// BM=128, BK=32, 256 threads = 8 warps (4M x 2N).

__device__ __forceinline__ uint32_t f2tf32(float f) {
    uint32_t u;
    asm("cvt.rna.tf32.f32 %0, %1;" : "=r"(u) : "f"(f));
    return u;
}

template <int OUTC, bool SCALE>
__global__ void k_gemm_tc(const float* __restrict__ X, const float* __restrict__ W,
                          const float* __restrict__ dinv, __half* __restrict__ out,
                          int N) {
    constexpr int BM = 128, BK = 32;
    constexpr int AP = 36;
    constexpr int WP = OUTC + 4;
    constexpr int WARP_N = OUTC / 2;
    constexpr int NNT = WARP_N / 8;
    __shared__ float As[BM * AP];
    __shared__ float Ws[BK * WP];

    const int tid  = threadIdx.x;
    const int warp = tid >> 5;
    const int lane = tid & 31;
    const int wm = warp >> 1;
    const int wn = warp & 1;
    const int g   = lane >> 2;
    const int tig = lane & 3;
    const int rowBase = blockIdx.x * BM;

    float acc[2][NNT][4];
#pragma unroll
    for (int mt = 0; mt < 2; mt++)
#pragma unroll
        for (int nt = 0; nt < NNT; nt++)
#pragma unroll
            for (int c = 0; c < 4; c++) acc[mt][nt][c] = 0.f;

    for (int k0 = 0; k0 < 128; k0 += BK) {
#pragma unroll
        for (int j = 0; j < 4; j++) {
            int i4  = tid + j * 256;
            int row = i4 >> 3;
            int col = (i4 & 7) * 4;
            float4 v = make_float4(0.f, 0.f, 0.f, 0.f);
            if (rowBase + row < N)
                v = *((const float4*)(X + (size_t)(rowBase + row) * 128 + k0 + col));
            float* p = &As[row * AP + col];
            p[0] = __uint_as_float(f2tf32(v.x));
            p[1] = __uint_as_float(f2tf32(v.y));
            p[2] = __uint_as_float(f2tf32(v.z));
            p[3] = __uint_as_float(f2tf32(v.w));
        }
        {
            constexpr int F4PR = OUTC / 4;
            constexpr int NJ = (BK * F4PR) / 256;
#pragma unroll
            for (int j = 0; j < NJ; j++) {
                int i4  = tid + j * 256;
                int row = i4 / F4PR;
                int col = (i4 % F4PR) * 4;
                float4 v = *((const float4*)(W + (size_t)(k0 + row) * OUTC + col));
                float* p = &Ws[row * WP + col];
                p[0] = __uint_as_float(f2tf32(v.x));
                p[1] = __uint_as_float(f2tf32(v.y));
                p[2] = __uint_as_float(f2tf32(v.z));
                p[3] = __uint_as_float(f2tf32(v.w));
            }
        }
        __syncthreads();

#pragma unroll
        for (int kk = 0; kk < BK / 8; kk++) {
            int k = kk * 8;
            uint32_t a[2][4];
#pragma unroll
            for (int mt = 0; mt < 2; mt++) {
                int ar = wm * 32 + mt * 16;
                a[mt][0] = __float_as_uint(As[(ar + g)     * AP + k + tig]);
                a[mt][1] = __float_as_uint(As[(ar + g + 8) * AP + k + tig]);
                a[mt][2] = __float_as_uint(As[(ar + g)     * AP + k + tig + 4]);
                a[mt][3] = __float_as_uint(As[(ar + g + 8) * AP + k + tig + 4]);
            }
#pragma unroll
            for (int nt = 0; nt < NNT; nt++) {
                int nc = wn * WARP_N + nt * 8;
                uint32_t b0 = __float_as_uint(Ws[(k + tig)     * WP + nc + g]);
                uint32_t b1 = __float_as_uint(Ws[(k + tig + 4) * WP + nc + g]);
#pragma unroll
                for (int mt = 0; mt < 2; mt++) {
                    asm volatile(
                        "mma.sync.aligned.m16n8k8.row.col.f32.tf32.tf32.f32 "
                        "{%0,%1,%2,%3}, {%4,%5,%6,%7}, {%8,%9}, {%0,%1,%2,%3};"
                        : "+f"(acc[mt][nt][0]), "+f"(acc[mt][nt][1]),
                          "+f"(acc[mt][nt][2]), "+f"(acc[mt][nt][3])
                        : "r"(a[mt][0]), "r"(a[mt][1]), "r"(a[mt][2]), "r"(a[mt][3]),
                          "r"(b0), "r"(b1));
                }
            }
        }
        __syncthreads();
    }

#pragma unroll
    for (int mt = 0; mt < 2; mt++) {
        int r0 = rowBase + wm * 32 + mt * 16 + g;
        int r1 = r0 + 8;
        float dv0 = 1.f, dv1 = 1.f;
        if (SCALE) {
            dv0 = (r0 < N) ? dinv[r0] : 0.f;
            dv1 = (r1 < N) ? dinv[r1] : 0.f;
        }
#pragma unroll
        for (int nt = 0; nt < NNT; nt++) {
            int col = wn * WARP_N + nt * 8 + tig * 2;
            if (r0 < N)
                *((__half2*)(out + (size_t)r0 * OUTC + col)) =
                    __floats2half2_rn(acc[mt][nt][0] * dv0, acc[mt][nt][1] * dv0);
            if (r1 < N)
                *((__half2*)(out + (size_t)r1 * OUTC + col)) =
                    __floats2half2_rn(acc[mt][nt][2] * dv1, acc[mt][nt][3] * dv1);
        }
    }
}

// ---------------- gathers ----------------
// Layer 1: msg is UNSCALED (x@W1). h1f = relu((Σ dinv[s]·msg[s] + dinv[n]·msg[n])·dinv[n] + b1)

__global__ void k_gather128h(const __half* __restrict__ g, const int* __restrict__ rowstart,
                             const int* __restrict__ srcs, const float* __restrict__ dinv,
                             const float* __restrict__ bias, float* __restrict__ out, int n) {
    int node = (blockIdx.x * blockDim.x + threadIdx.x) >> 5;
    int lane = threadIdx.x & 31;
    if (node >= n) return;
    int e0 = rowstart[node], e1 = rowstart[node + 1];
    float dvn = dinv[node];

    float acc0, acc1, acc2, acc3;
    {   // self-loop term, scaled by dinv[node]
        uint2 u = *((const uint2*)(g + (size_t)node * 128 + lane * 4));
        float2 a = __half22float2(*(const __half2*)&u.x);
        float2 b = __half22float2(*(const __half2*)&u.y);
        acc0 = dvn * a.x; acc1 = dvn * a.y; acc2 = dvn * b.x; acc3 = dvn * b.y;
    }
    int e = e0;
    // fast path: full 32-edge batches, no predicates
    while (e1 - e >= 32) {
        int idx = srcs[e + lane];
        float dvl = dinv[idx];
#pragma unroll
        for (int k = 0; k < 32; k++) {
            int s    = __shfl_sync(0xffffffffu, idx, k);
            float ds = __shfl_sync(0xffffffffu, dvl, k);
            uint2 u = *((const uint2*)(g + (size_t)s * 128 + lane * 4));
            float2 a = __half22float2(*(const __half2*)&u.x);
            float2 b = __half22float2(*(const __half2*)&u.y);
            acc0 += ds * a.x; acc1 += ds * a.y; acc2 += ds * b.x; acc3 += ds * b.y;
        }
        e += 32;
    }
    // tail
    if (e < e1) {
        int m = e1 - e;
        int idx = (lane < m) ? srcs[e + lane] : 0;
        float dvl = (lane < m) ? dinv[idx] : 0.f;
#pragma unroll 8
        for (int k = 0; k < m; k++) {
            int s    = __shfl_sync(0xffffffffu, idx, k);
            float ds = __shfl_sync(0xffffffffu, dvl, k);
            uint2 u = *((const uint2*)(g + (size_t)s * 128 + lane * 4));
            float2 a = __half22float2(*(const __half2*)&u.x);
            float2 b = __half22float2(*(const __half2*)&u.y);
            acc0 += ds * a.x; acc1 += ds * a.y; acc2 += ds * b.x; acc3 += ds * b.y;
        }
    }
    float4 bv = ((const float4*)bias)[lane];
    float4 r;
    r.x = fmaxf(acc0 * dvn + bv.x, 0.f);
    r.y = fmaxf(acc1 * dvn + bv.y, 0.f);
    r.z = fmaxf(acc2 * dvn + bv.z, 0.f);
    r.w = fmaxf(acc3 * dvn + bv.w, 0.f);
    ((float4*)(out + (size_t)node * 128))[lane] = r;
}

// Layer 2: msg is dinv-scaled already (GEMM2 folds it). out = (Σ msg[s] + msg[n])·dinv[n] + b2
__global__ void k_gather64h(const __half* __restrict__ g, const int* __restrict__ rowstart,
                            const int* __restrict__ srcs, const float* __restrict__ dinv,
                            const float* __restrict__ bias, float* __restrict__ out, int n) {
    int node = (blockIdx.x * blockDim.x + threadIdx.x) >> 5;
    int lane = threadIdx.x & 31;
    if (node >= n) return;
    int e0 = rowstart[node], e1 = rowstart[node + 1];

    float2 acc = __half22float2(*((const __half2*)(g + (size_t)node * 64 + lane * 2)));
    int e = e0;
    while (e1 - e >= 32) {
        int idx = srcs[e + lane];
#pragma unroll
        for (int k = 0; k < 32; k++) {
            int s = __shfl_sync(0xffffffffu, idx, k);
            float2 v = __half22float2(*((const __half2*)(g + (size_t)s * 64 + lane * 2)));
            acc.x += v.x; acc.y += v.y;
        }
        e += 32;
    }
    if (e < e1) {
        int m = e1 - e;
        int idx = (lane < m) ? srcs[e + lane] : 0;
#pragma unroll 8
        for (int k = 0; k < m; k++) {
            int s = __shfl_sync(0xffffffffu, idx, k);
            float2 v = __half22float2(*((const __half2*)(g + (size_t)s * 64 + lane * 2)));
            acc.x += v.x; acc.y += v.y;
        }
    }
    float dv = dinv[node];
    float2 bv = ((const float2*)bias)[lane];
    float2 r;
    r.x = acc.x * dv + bv.x;
    r.y = acc.y * dv + bv.y;
    ((float2*)(out + (size_t)node * 64))[lane] = r;
}

// ---------------- launch ----------------

extern "C" void kernel_launch(void* const* d_in, const int* in_sizes, int n_in,
                              void* d_out, int out_size) {
    const float* x   = (const float*)d_in[0];
    const int*   ei  = (const int*)d_in[1];    // int32 (JAX x64 disabled)
    const float* W1  = (const float*)d_in[2];
    const float* b1  = (const float*)d_in[3];
    const float* W2  = (const float*)d_in[4];
    const float* b2  = (const float*)d_in[5];
    float*       out = (float*)d_out;

    const int N = in_sizes[0] / 128;
    const int E = in_sizes[1] / 2;
    const int* srcp = ei;
    const int* dstp = ei + E;

    float*  dinv;  cudaGetSymbolAddress((void**)&dinv,  g_dinv);
    int*    count; cudaGetSymbolAddress((void**)&count, g_count);
    int*    rowst; cudaGetSymbolAddress((void**)&rowst, g_rowstart);
    int*    rank;  cudaGetSymbolAddress((void**)&rank,  g_rank);
    int*    bsum;  cudaGetSymbolAddress((void**)&bsum,  g_blocksum);
    int*    srcs;  cudaGetSymbolAddress((void**)&srcs,  g_srcs);
    __half* msg;   cudaGetSymbolAddress((void**)&msg,   g_msg);
    float*  h1f;   cudaGetSymbolAddress((void**)&h1f,   g_h1f);

    // one-time host-side resources (no device memory)
    static cudaStream_t s2 = nullptr;
    static cudaEvent_t evRoot = nullptr, evG1 = nullptr;
    if (!s2) {
        cudaStreamCreateWithFlags(&s2, cudaStreamNonBlocking);
        cudaEventCreateWithFlags(&evRoot, cudaEventDisableTiming);
        cudaEventCreateWithFlags(&evG1, cudaEventDisableTiming);
    }

    const int T = 256;
    const int nb = (N + SCAN_B - 1) / SCAN_B;

    // fork: GEMM1 (independent of CSR build — msg unscaled) on s2
    cudaEventRecord(evRoot, 0);
    cudaStreamWaitEvent(s2, evRoot, 0);
    k_gemm_tc<128, false><<<(N + 127) / 128, 256, 0, s2>>>(x, W1, nullptr, msg, N);
    cudaEventRecord(evG1, s2);

    // CSR build (stream 0)
    k_zero_int<<<(N + T - 1) / T, T>>>(count, N);
    k_hist<<<(E + T - 1) / T, T>>>(dstp, count, rank, E, N);
    k_scan1<<<nb, SCAN_B>>>(count, rowst, bsum, N);
    k_scan2<<<1, 32>>>(bsum, nb);
    k_scan3<<<(N + T - 1) / T, T>>>(count, rowst, bsum, dinv, N, E);
    k_fill<<<(E + T - 1) / T, T>>>(srcp, dstp, rowst, rank, srcs, E, N);

    // join: gather1 needs CSR + GEMM1
    cudaStreamWaitEvent(0, evG1, 0);
    k_gather128h<<<(N * 32 + T - 1) / T, T>>>(msg, rowst, srcs, dinv, b1, h1f, N);

    // layer 2: g2 = half((h1f@W2)*dinv) -> msg ; out = gather(g2)+b2
    k_gemm_tc<64, true><<<(N + 127) / 128, 256>>>(h1f, W2, dinv, msg, N);
    k_gather64h<<<(N * 32 + T - 1) / T, T>>>(msg, rowst, srcs, dinv, b2, out, N);
}